// round 7
// baseline (speedup 1.0000x reference)
#include <cuda_runtime.h>
#include <cuda_bf16.h>
#include <math.h>
#include <stdint.h>

// ---------------------------------------------------------------------------
// Problem constants
// ---------------------------------------------------------------------------
#define BATCH   2048
#define T_SEQ   64
#define D_MODEL 384
#define NH      8
#define HS      48
#define D_FF    1536
#define M_TOK   (BATCH * T_SEQ)          // 131072
#define QKV_N   (3 * D_MODEL)            // 1152

// ---------------------------------------------------------------------------
// Scratch (static device globals)
// ---------------------------------------------------------------------------
__device__ float          g_h1  [(size_t)M_TOK * D_MODEL];
__device__ __nv_bfloat16  g_h1b [(size_t)M_TOK * D_MODEL];
__device__ float          g_h2  [(size_t)M_TOK * D_MODEL];
__device__ __nv_bfloat16  g_h2b [(size_t)M_TOK * D_MODEL];
__device__ float          g_res [(size_t)M_TOK * D_MODEL];
__device__ float          g_big [(size_t)M_TOK * QKV_N];    // QKV fp32
__device__ __nv_bfloat16  g_attnb[(size_t)M_TOK * D_MODEL]; // attn out bf16
__device__ __nv_bfloat16  g_midb[(size_t)M_TOK * D_FF];     // FF mid bf16
__device__ __nv_bfloat16  g_WqkvT[(size_t)QKV_N * D_MODEL]; // [1152][384] bf16
__device__ float          g_bqkv [QKV_N];
__device__ __nv_bfloat16  g_WoT  [(size_t)D_MODEL * D_MODEL];
__device__ __nv_bfloat16  g_W1T  [(size_t)D_FF * D_MODEL];
__device__ __nv_bfloat16  g_W2T  [(size_t)D_MODEL * D_FF];

// ---------------------------------------------------------------------------
// Helpers
// ---------------------------------------------------------------------------
__device__ __forceinline__ uint32_t smem_u32(const void* p) {
    uint32_t a;
    asm("{ .reg .u64 t; cvta.to.shared.u64 t, %1; cvt.u32.u64 %0, t; }" : "=r"(a) : "l"(p));
    return a;
}
__device__ __forceinline__ void cp16(uint32_t dst, const void* src) {
    asm volatile("cp.async.cg.shared.global [%0], [%1], 16;" :: "r"(dst), "l"(src));
}
__device__ __forceinline__ void ldsm_x4(uint32_t& r0, uint32_t& r1, uint32_t& r2, uint32_t& r3,
                                        uint32_t addr) {
    asm volatile("ldmatrix.sync.aligned.m8n8.x4.shared.b16 {%0,%1,%2,%3}, [%4];"
                 : "=r"(r0), "=r"(r1), "=r"(r2), "=r"(r3) : "r"(addr));
}
__device__ __forceinline__ void mma_bf16(float* c, const uint32_t* a, const uint32_t* b) {
    asm volatile(
        "mma.sync.aligned.m16n8k16.row.col.f32.bf16.bf16.f32 "
        "{%0,%1,%2,%3}, {%4,%5,%6,%7}, {%8,%9}, {%0,%1,%2,%3};"
        : "+f"(c[0]), "+f"(c[1]), "+f"(c[2]), "+f"(c[3])
        : "r"(a[0]), "r"(a[1]), "r"(a[2]), "r"(a[3]), "r"(b[0]), "r"(b[1]));
}
__device__ __forceinline__ void mma_tf32(float* c, const uint32_t* a, const uint32_t* b) {
    asm volatile(
        "mma.sync.aligned.m16n8k8.row.col.f32.tf32.tf32.f32 "
        "{%0,%1,%2,%3}, {%4,%5,%6,%7}, {%8,%9}, {%0,%1,%2,%3};"
        : "+f"(c[0]), "+f"(c[1]), "+f"(c[2]), "+f"(c[3])
        : "r"(a[0]), "r"(a[1]), "r"(a[2]), "r"(a[3]), "r"(b[0]), "r"(b[1]));
}
__device__ __forceinline__ uint32_t f2tf32(float f) {
    uint32_t u;
    asm("cvt.rna.tf32.f32 %0, %1;" : "=r"(u) : "f"(f));
    return u;
}
__device__ __forceinline__ uint32_t packbf(float x, float y) {
    __nv_bfloat162 p = __floats2bfloat162_rn(x, y);
    return *(uint32_t*)&p;
}

// ---------------------------------------------------------------------------
// Weight repack kernels (fp32 -> bf16, transposed to [N][K] K-major)
// ---------------------------------------------------------------------------
__global__ void pack_qkvT_kernel(const float* __restrict__ wq, const float* __restrict__ wk,
                                 const float* __restrict__ wv, const float* __restrict__ bq,
                                 const float* __restrict__ bk, const float* __restrict__ bv) {
    int i = blockIdx.x * blockDim.x + threadIdx.x;
    const int total = QKV_N * D_MODEL;
    if (i < total) {
        int col = i / D_MODEL;
        int d   = i % D_MODEL;
        int which = col / D_MODEL;
        int hc    = col % D_MODEL;
        int h = hc / HS, e = hc % HS;
        const float* w = (which == 0) ? wq : (which == 1) ? wk : wv;
        g_WqkvT[i] = __float2bfloat16(w[((size_t)h * D_MODEL + d) * HS + e]);
    }
    if (i < QKV_N) {
        int which = i / D_MODEL;
        int hc    = i % D_MODEL;
        int h = hc / HS, e = hc % HS;
        const float* bsrc = (which == 0) ? bq : (which == 1) ? bk : bv;
        g_bqkv[i] = bsrc[h * HS + e];
    }
}

__global__ void transpose_bf_kernel(const float* __restrict__ src, __nv_bfloat16* __restrict__ dst,
                                    int Kd, int Nd) {
    int i = blockIdx.x * blockDim.x + threadIdx.x;
    if (i < Kd * Nd) {
        int n = i / Kd, k = i % Kd;
        dst[i] = __float2bfloat16(src[(size_t)k * Nd + n]);
    }
}

// ---------------------------------------------------------------------------
// LayerNorm: one warp per token row; writes fp32 AND bf16 outputs
// ---------------------------------------------------------------------------
__global__ void ln_kernel(const float* __restrict__ in, const float* __restrict__ gain,
                          const float* __restrict__ bias, float* __restrict__ out,
                          __nv_bfloat16* __restrict__ outb) {
    int warp = (blockIdx.x * blockDim.x + threadIdx.x) >> 5;
    int lane = threadIdx.x & 31;
    if (warp >= M_TOK) return;
    const float4* row = (const float4*)(in + (size_t)warp * D_MODEL);
    float4 v[3];
    float s = 0.f, s2 = 0.f;
#pragma unroll
    for (int j = 0; j < 3; j++) {
        v[j] = row[lane + 32 * j];
        s  += v[j].x + v[j].y + v[j].z + v[j].w;
        s2 += v[j].x * v[j].x + v[j].y * v[j].y + v[j].z * v[j].z + v[j].w * v[j].w;
    }
#pragma unroll
    for (int o = 16; o; o >>= 1) {
        s  += __shfl_xor_sync(0xffffffffu, s,  o);
        s2 += __shfl_xor_sync(0xffffffffu, s2, o);
    }
    float mean = s * (1.0f / D_MODEL);
    float var  = s2 * (1.0f / D_MODEL) - mean * mean;
    float inv  = rsqrtf(var + 1e-5f);
    float4* orow = (float4*)(out + (size_t)warp * D_MODEL);
    __nv_bfloat16* brow = outb + (size_t)warp * D_MODEL;
#pragma unroll
    for (int j = 0; j < 3; j++) {
        int idx = lane + 32 * j;
        float4 g4 = ((const float4*)gain)[idx];
        float4 b4 = ((const float4*)bias)[idx];
        float4 o;
        o.x = (v[j].x - mean) * inv * g4.x + b4.x;
        o.y = (v[j].y - mean) * inv * g4.y + b4.y;
        o.z = (v[j].z - mean) * inv * g4.z + b4.z;
        o.w = (v[j].w - mean) * inv * g4.w + b4.w;
        orow[idx] = o;
        uint2 packed;
        packed.x = packbf(o.x, o.y);
        packed.y = packbf(o.z, o.w);
        *(uint2*)&brow[idx * 4] = packed;
    }
}

// ---------------------------------------------------------------------------
// bf16 HMMA GEMM: 128x128, BK=32, 256 thr, cp.async x2, ldmatrix frag loads
// ---------------------------------------------------------------------------
#define BK  32
#define AST 40   // padded smem row stride (80B): ldmatrix rows cover all 32 banks

template <bool BIAS, bool RES, bool RELU, bool OUTBF>
__global__ __launch_bounds__(256)
void bgemm(const __nv_bfloat16* __restrict__ A, const __nv_bfloat16* __restrict__ Bw,
           const float* __restrict__ bias, const float* __restrict__ Rsd,
           void* __restrict__ Cout, int N, int K) {
    __shared__ __nv_bfloat16 As[2][128 * AST];
    __shared__ __nv_bfloat16 Bs[2][128 * AST];

    const int tid = threadIdx.x;
    const int lane = tid & 31, warp = tid >> 5;
    const int warp_m = warp & 1, warp_n = warp >> 1;
    const int g = lane >> 2, tg = lane & 3;
    const int bm = blockIdx.y * 128, bn = blockIdx.x * 128;

    const uint32_t sA[2] = { smem_u32(As[0]), smem_u32(As[1]) };
    const uint32_t sB[2] = { smem_u32(Bs[0]), smem_u32(Bs[1]) };

    // ldmatrix.x4 per-lane source row: tile t = lane/8, row-in-tile = lane%8
    // tile order: (row_half 0, k_half 0), (row_half 1, k_half 0),
    //             (row_half 0, k_half 1), (row_half 1, k_half 1)
    const int l8 = lane >> 3;
    const int lm_row  = ((l8 & 1) << 3) + (lane & 7);  // 0..15 within 16-row group
    const int lm_khalf = (l8 >> 1) << 3;               // 0 or 8

    auto issue = [&](int k0, int buf) {
#pragma unroll
        for (int i = 0; i < 2; i++) {
            int idx = tid + i * 256;
            int row = idx >> 2, seg = idx & 3;
            cp16(sA[buf] + (row * AST + seg * 8) * 2,
                 A + (size_t)(bm + row) * K + k0 + seg * 8);
        }
#pragma unroll
        for (int i = 0; i < 2; i++) {
            int idx = tid + i * 256;
            int row = idx >> 2, seg = idx & 3;
            cp16(sB[buf] + (row * AST + seg * 8) * 2,
                 Bw + (size_t)(bn + row) * K + k0 + seg * 8);
        }
        asm volatile("cp.async.commit_group;" ::: "memory");
    };

    float acc[4][4][4] = {};

    issue(0, 0);
    const int NC = K / BK;
    for (int c = 0; c < NC; c++) {
        const int buf = c & 1;
        if (c + 1 < NC) {
            issue((c + 1) * BK, buf ^ 1);
            asm volatile("cp.async.wait_group 1;" ::: "memory");
        } else {
            asm volatile("cp.async.wait_group 0;" ::: "memory");
        }
        __syncthreads();

#pragma unroll
        for (int ks = 0; ks < BK; ks += 16) {
            uint32_t afr[4][4], bfr[4][2];
#pragma unroll
            for (int mt = 0; mt < 4; mt++) {
                uint32_t addr = sA[buf] +
                    ((warp_m * 64 + mt * 16 + lm_row) * AST + ks + lm_khalf) * 2;
                ldsm_x4(afr[mt][0], afr[mt][1], afr[mt][2], afr[mt][3], addr);
            }
#pragma unroll
            for (int nb = 0; nb < 2; nb++) {
                uint32_t r0, r1, r2, r3;
                uint32_t addr = sB[buf] +
                    ((warp_n * 32 + nb * 16 + lm_row) * AST + ks + lm_khalf) * 2;
                ldsm_x4(r0, r1, r2, r3, addr);
                bfr[nb * 2][0]     = r0;  bfr[nb * 2][1]     = r2;
                bfr[nb * 2 + 1][0] = r1;  bfr[nb * 2 + 1][1] = r3;
            }
#pragma unroll
            for (int mt = 0; mt < 4; mt++)
#pragma unroll
                for (int nt = 0; nt < 4; nt++)
                    mma_bf16(acc[mt][nt], afr[mt], bfr[nt]);
        }
        __syncthreads();
    }

    float* Cf = (float*)Cout;
    __nv_bfloat16* Cb = (__nv_bfloat16*)Cout;
#pragma unroll
    for (int mt = 0; mt < 4; mt++) {
#pragma unroll
        for (int half = 0; half < 2; half++) {
            int row = bm + warp_m * 64 + mt * 16 + g + half * 8;
#pragma unroll
            for (int nt = 0; nt < 4; nt++) {
                int col = bn + warp_n * 32 + nt * 8 + tg * 2;
                float vx = acc[mt][nt][half * 2 + 0];
                float vy = acc[mt][nt][half * 2 + 1];
                if (BIAS) {
                    float2 b2 = *(const float2*)&bias[col];
                    vx += b2.x; vy += b2.y;
                }
                if (RELU) { vx = fmaxf(vx, 0.f); vy = fmaxf(vy, 0.f); }
                if (RES) {
                    float2 r2 = *(const float2*)&Rsd[(size_t)row * N + col];
                    vx += r2.x; vy += r2.y;
                }
                if (OUTBF) {
                    *(uint32_t*)&Cb[(size_t)row * N + col] = packbf(vx, vy);
                } else {
                    *(float2*)&Cf[(size_t)row * N + col] = make_float2(vx, vy);
                }
            }
        }
    }
}

// ---------------------------------------------------------------------------
// Tensor-core causal attention (unchanged from R6)
// ---------------------------------------------------------------------------
__global__ __launch_bounds__(128) void attn_kernel(__nv_bfloat16* __restrict__ out) {
    const int bh = blockIdx.x;
    const int b = bh >> 3, h = bh & 7;
    const float* qkv = g_big;

    __shared__ float qs[T_SEQ][52];
    __shared__ float ksm[T_SEQ][52];
    __shared__ __nv_bfloat16 vt[HS][72];

    const int tid = threadIdx.x;
    const int lane = tid & 31, warp = tid >> 5;
    const int g = lane >> 2, tg = lane & 3;

    for (int i = tid; i < T_SEQ * 12; i += 128) {
        int r = i / 12, c4 = (i % 12) * 4;
        size_t base = (size_t)(b * T_SEQ + r) * QKV_N + h * HS + c4;
        *(float4*)&qs[r][c4]  = *(const float4*)&qkv[base];
        *(float4*)&ksm[r][c4] = *(const float4*)&qkv[base + D_MODEL];
        float4 v4 = *(const float4*)&qkv[base + 2 * D_MODEL];
        vt[c4 + 0][r] = __float2bfloat16(v4.x);
        vt[c4 + 1][r] = __float2bfloat16(v4.y);
        vt[c4 + 2][r] = __float2bfloat16(v4.z);
        vt[c4 + 3][r] = __float2bfloat16(v4.w);
    }
    __syncthreads();

    const int m0 = warp * 16;

    float sacc[8][4] = {};
#pragma unroll
    for (int ks = 0; ks < HS; ks += 8) {
        uint32_t a[4];
        a[0] = f2tf32(qs[m0 + g][ks + tg]);
        a[1] = f2tf32(qs[m0 + g + 8][ks + tg]);
        a[2] = f2tf32(qs[m0 + g][ks + tg + 4]);
        a[3] = f2tf32(qs[m0 + g + 8][ks + tg + 4]);
#pragma unroll
        for (int nt = 0; nt < 8; nt++) {
            uint32_t bf[2];
            bf[0] = f2tf32(ksm[nt * 8 + g][ks + tg]);
            bf[1] = f2tf32(ksm[nt * 8 + g][ks + tg + 4]);
            mma_tf32(sacc[nt], a, bf);
        }
    }

    const float scale = 0.14433756729740643f;
    const int row0 = m0 + g, row1 = m0 + g + 8;
    float mx0 = -1e30f, mx1 = -1e30f;
#pragma unroll
    for (int nt = 0; nt < 8; nt++) {
#pragma unroll
        for (int j = 0; j < 2; j++) {
            int col = nt * 8 + tg * 2 + j;
            float s0 = sacc[nt][j] * scale;
            float s1 = sacc[nt][2 + j] * scale;
            if (col > row0) s0 = -1e30f;
            if (col > row1) s1 = -1e30f;
            sacc[nt][j] = s0;     sacc[nt][2 + j] = s1;
            mx0 = fmaxf(mx0, s0); mx1 = fmaxf(mx1, s1);
        }
    }
    mx0 = fmaxf(mx0, __shfl_xor_sync(0xffffffffu, mx0, 1));
    mx0 = fmaxf(mx0, __shfl_xor_sync(0xffffffffu, mx0, 2));
    mx1 = fmaxf(mx1, __shfl_xor_sync(0xffffffffu, mx1, 1));
    mx1 = fmaxf(mx1, __shfl_xor_sync(0xffffffffu, mx1, 2));

    float sum0 = 0.f, sum1 = 0.f;
#pragma unroll
    for (int nt = 0; nt < 8; nt++) {
#pragma unroll
        for (int j = 0; j < 2; j++) {
            float e0 = __expf(sacc[nt][j] - mx0);
            float e1 = __expf(sacc[nt][2 + j] - mx1);
            sacc[nt][j] = e0;     sacc[nt][2 + j] = e1;
            sum0 += e0;           sum1 += e1;
        }
    }
    sum0 += __shfl_xor_sync(0xffffffffu, sum0, 1);
    sum0 += __shfl_xor_sync(0xffffffffu, sum0, 2);
    sum1 += __shfl_xor_sync(0xffffffffu, sum1, 1);
    sum1 += __shfl_xor_sync(0xffffffffu, sum1, 2);
    const float inv0 = 1.0f / sum0, inv1 = 1.0f / sum1;

    float o[6][4] = {};
#pragma unroll
    for (int ks = 0; ks < 4; ks++) {
        uint32_t a[4];
        a[0] = packbf(sacc[2 * ks][0],     sacc[2 * ks][1]);
        a[1] = packbf(sacc[2 * ks][2],     sacc[2 * ks][3]);
        a[2] = packbf(sacc[2 * ks + 1][0], sacc[2 * ks + 1][1]);
        a[3] = packbf(sacc[2 * ks + 1][2], sacc[2 * ks + 1][3]);
#pragma unroll
        for (int nt = 0; nt < 6; nt++) {
            uint32_t bf[2];
            bf[0] = *(const uint32_t*)&vt[nt * 8 + g][ks * 16 + tg * 2];
            bf[1] = *(const uint32_t*)&vt[nt * 8 + g][ks * 16 + 8 + tg * 2];
            mma_bf16(o[nt], a, bf);
        }
    }

    const size_t ob0 = (size_t)(b * T_SEQ + row0) * D_MODEL + h * HS;
    const size_t ob1 = (size_t)(b * T_SEQ + row1) * D_MODEL + h * HS;
#pragma unroll
    for (int nt = 0; nt < 6; nt++) {
        int col = nt * 8 + tg * 2;
        *(uint32_t*)&out[ob0 + col] = packbf(o[nt][0] * inv0, o[nt][1] * inv0);
        *(uint32_t*)&out[ob1 + col] = packbf(o[nt][2] * inv1, o[nt][3] * inv1);
    }
}

// ---------------------------------------------------------------------------
// Launcher
// ---------------------------------------------------------------------------
extern "C" void kernel_launch(void* const* d_in, const int* in_sizes, int n_in,
                              void* d_out, int out_size) {
    (void)in_sizes; (void)n_in; (void)out_size;
    const float* x  = (const float*)d_in[0];
    const float* wq = (const float*)d_in[1];
    const float* bq = (const float*)d_in[2];
    const float* wk = (const float*)d_in[3];
    const float* bk = (const float*)d_in[4];
    const float* wv = (const float*)d_in[5];
    const float* bv = (const float*)d_in[6];
    const float* wo = (const float*)d_in[7];
    const float* bo = (const float*)d_in[8];
    const float* w1 = (const float*)d_in[9];
    const float* b1 = (const float*)d_in[10];
    const float* w2 = (const float*)d_in[11];
    const float* b2 = (const float*)d_in[12];
    const float* g1 = (const float*)d_in[13];
    const float* be1 = (const float*)d_in[14];
    const float* g2 = (const float*)d_in[15];
    const float* be2 = (const float*)d_in[16];
    float* out = (float*)d_out;

    float *p_h1, *p_h2, *p_res, *p_big, *p_bqkv;
    __nv_bfloat16 *p_h1b, *p_h2b, *p_attnb, *p_midb, *p_WqkvT, *p_WoT, *p_W1T, *p_W2T;
    cudaGetSymbolAddress((void**)&p_h1, g_h1);
    cudaGetSymbolAddress((void**)&p_h1b, g_h1b);
    cudaGetSymbolAddress((void**)&p_h2, g_h2);
    cudaGetSymbolAddress((void**)&p_h2b, g_h2b);
    cudaGetSymbolAddress((void**)&p_res, g_res);
    cudaGetSymbolAddress((void**)&p_big, g_big);
    cudaGetSymbolAddress((void**)&p_attnb, g_attnb);
    cudaGetSymbolAddress((void**)&p_midb, g_midb);
    cudaGetSymbolAddress((void**)&p_WqkvT, g_WqkvT);
    cudaGetSymbolAddress((void**)&p_bqkv, g_bqkv);
    cudaGetSymbolAddress((void**)&p_WoT, g_WoT);
    cudaGetSymbolAddress((void**)&p_W1T, g_W1T);
    cudaGetSymbolAddress((void**)&p_W2T, g_W2T);

    // 0. weight repacks -> bf16 [N][K]
    pack_qkvT_kernel<<<(QKV_N * D_MODEL + 255) / 256, 256>>>(wq, wk, wv, bq, bk, bv);
    transpose_bf_kernel<<<(D_MODEL * D_MODEL + 255) / 256, 256>>>(wo, p_WoT, D_MODEL, D_MODEL);
    transpose_bf_kernel<<<(D_MODEL * D_FF + 255) / 256, 256>>>(w1, p_W1T, D_MODEL, D_FF);
    transpose_bf_kernel<<<(D_FF * D_MODEL + 255) / 256, 256>>>(w2, p_W2T, D_FF, D_MODEL);

    // 1. LN1: x -> h1 (fp32) + h1b (bf16)
    ln_kernel<<<(M_TOK * 32) / 256, 256>>>(x, g1, be1, p_h1, p_h1b);

    // 2. QKV GEMM: h1b @ WqkvT^T + bqkv -> g_big (fp32)
    bgemm<true, false, false, false><<<dim3(QKV_N / 128, M_TOK / 128), 256>>>(
        p_h1b, p_WqkvT, p_bqkv, nullptr, p_big, QKV_N, D_MODEL);

    // 3. attention (tensor-core) -> attnb (bf16)
    attn_kernel<<<BATCH * NH, 128>>>(p_attnb);

    // 4. output projection + residual: attnb @ WoT^T + bo + h1 -> res (fp32)
    bgemm<true, true, false, false><<<dim3(D_MODEL / 128, M_TOK / 128), 256>>>(
        p_attnb, p_WoT, bo, p_h1, p_res, D_MODEL, D_MODEL);

    // 5. LN2: res -> h2 (fp32) + h2b (bf16)
    ln_kernel<<<(M_TOK * 32) / 256, 256>>>(p_res, g2, be2, p_h2, p_h2b);

    // 6. FF1 + ReLU: h2b @ W1T^T + b1 -> midb (bf16)
    bgemm<true, false, true, true><<<dim3(D_FF / 128, M_TOK / 128), 256>>>(
        p_h2b, p_W1T, b1, nullptr, p_midb, D_FF, D_MODEL);

    // 7. FF2 + bias + residual: midb @ W2T^T + b2 + h2 -> out (fp32)
    bgemm<true, true, false, false><<<dim3(D_MODEL / 128, M_TOK / 128), 256>>>(
        p_midb, p_W2T, b2, p_h2, out, D_MODEL, D_FF);
}

// round 8
// speedup vs baseline: 1.0618x; 1.0618x over previous
#include <cuda_runtime.h>
#include <cuda_bf16.h>
#include <math.h>
#include <stdint.h>

// ---------------------------------------------------------------------------
// Problem constants
// ---------------------------------------------------------------------------
#define BATCH   2048
#define T_SEQ   64
#define D_MODEL 384
#define NH      8
#define HS      48
#define D_FF    1536
#define M_TOK   (BATCH * T_SEQ)          // 131072
#define QKV_N   (3 * D_MODEL)            // 1152

// ---------------------------------------------------------------------------
// Scratch (static device globals)
// ---------------------------------------------------------------------------
__device__ float          g_h1  [(size_t)M_TOK * D_MODEL];
__device__ __nv_bfloat16  g_h1b [(size_t)M_TOK * D_MODEL];
__device__ float          g_h2  [(size_t)M_TOK * D_MODEL];
__device__ __nv_bfloat16  g_h2b [(size_t)M_TOK * D_MODEL];
__device__ float          g_big [(size_t)M_TOK * QKV_N];    // QKV fp32
__device__ __nv_bfloat16  g_attnb[(size_t)M_TOK * D_MODEL]; // attn out bf16
__device__ __nv_bfloat16  g_midb[(size_t)M_TOK * D_FF];     // FF mid bf16
__device__ __nv_bfloat16  g_WqkvT[(size_t)QKV_N * D_MODEL]; // [1152][384] bf16
__device__ float          g_bqkv [QKV_N];
__device__ __nv_bfloat16  g_WoT  [(size_t)D_MODEL * D_MODEL];
__device__ __nv_bfloat16  g_W1T  [(size_t)D_FF * D_MODEL];
__device__ __nv_bfloat16  g_W2T  [(size_t)D_MODEL * D_FF];

// ---------------------------------------------------------------------------
// Helpers
// ---------------------------------------------------------------------------
__device__ __forceinline__ uint32_t smem_u32(const void* p) {
    uint32_t a;
    asm("{ .reg .u64 t; cvta.to.shared.u64 t, %1; cvt.u32.u64 %0, t; }" : "=r"(a) : "l"(p));
    return a;
}
__device__ __forceinline__ void cp16(uint32_t dst, const void* src) {
    asm volatile("cp.async.cg.shared.global [%0], [%1], 16;" :: "r"(dst), "l"(src));
}
__device__ __forceinline__ void mma_bf16(float* c, const uint32_t* a, const uint32_t* b) {
    asm volatile(
        "mma.sync.aligned.m16n8k16.row.col.f32.bf16.bf16.f32 "
        "{%0,%1,%2,%3}, {%4,%5,%6,%7}, {%8,%9}, {%0,%1,%2,%3};"
        : "+f"(c[0]), "+f"(c[1]), "+f"(c[2]), "+f"(c[3])
        : "r"(a[0]), "r"(a[1]), "r"(a[2]), "r"(a[3]), "r"(b[0]), "r"(b[1]));
}
__device__ __forceinline__ void mma_tf32(float* c, const uint32_t* a, const uint32_t* b) {
    asm volatile(
        "mma.sync.aligned.m16n8k8.row.col.f32.tf32.tf32.f32 "
        "{%0,%1,%2,%3}, {%4,%5,%6,%7}, {%8,%9}, {%0,%1,%2,%3};"
        : "+f"(c[0]), "+f"(c[1]), "+f"(c[2]), "+f"(c[3])
        : "r"(a[0]), "r"(a[1]), "r"(a[2]), "r"(a[3]), "r"(b[0]), "r"(b[1]));
}
__device__ __forceinline__ uint32_t f2tf32(float f) {
    uint32_t u;
    asm("cvt.rna.tf32.f32 %0, %1;" : "=r"(u) : "f"(f));
    return u;
}
__device__ __forceinline__ uint32_t packbf(float x, float y) {
    __nv_bfloat162 p = __floats2bfloat162_rn(x, y);
    return *(uint32_t*)&p;
}

// ---------------------------------------------------------------------------
// Weight repack kernels (fp32 -> bf16, transposed to [N][K] K-major)
// ---------------------------------------------------------------------------
__global__ void pack_qkvT_kernel(const float* __restrict__ wq, const float* __restrict__ wk,
                                 const float* __restrict__ wv, const float* __restrict__ bq,
                                 const float* __restrict__ bk, const float* __restrict__ bv) {
    int i = blockIdx.x * blockDim.x + threadIdx.x;
    const int total = QKV_N * D_MODEL;
    if (i < total) {
        int col = i / D_MODEL;
        int d   = i % D_MODEL;
        int which = col / D_MODEL;
        int hc    = col % D_MODEL;
        int h = hc / HS, e = hc % HS;
        const float* w = (which == 0) ? wq : (which == 1) ? wk : wv;
        g_WqkvT[i] = __float2bfloat16(w[((size_t)h * D_MODEL + d) * HS + e]);
    }
    if (i < QKV_N) {
        int which = i / D_MODEL;
        int hc    = i % D_MODEL;
        int h = hc / HS, e = hc % HS;
        const float* bsrc = (which == 0) ? bq : (which == 1) ? bk : bv;
        g_bqkv[i] = bsrc[h * HS + e];
    }
}

__global__ void transpose_bf_kernel(const float* __restrict__ src, __nv_bfloat16* __restrict__ dst,
                                    int Kd, int Nd) {
    int i = blockIdx.x * blockDim.x + threadIdx.x;
    if (i < Kd * Nd) {
        int n = i / Kd, k = i % Kd;
        dst[i] = __float2bfloat16(src[(size_t)k * Nd + n]);
    }
}

// ---------------------------------------------------------------------------
// LayerNorm: one warp per token row; writes fp32 AND bf16 outputs
// ---------------------------------------------------------------------------
__global__ void ln_kernel(const float* __restrict__ in, const float* __restrict__ gain,
                          const float* __restrict__ bias, float* __restrict__ out,
                          __nv_bfloat16* __restrict__ outb) {
    int warp = (blockIdx.x * blockDim.x + threadIdx.x) >> 5;
    int lane = threadIdx.x & 31;
    if (warp >= M_TOK) return;
    const float4* row = (const float4*)(in + (size_t)warp * D_MODEL);
    float4 v[3];
    float s = 0.f, s2 = 0.f;
#pragma unroll
    for (int j = 0; j < 3; j++) {
        v[j] = row[lane + 32 * j];
        s  += v[j].x + v[j].y + v[j].z + v[j].w;
        s2 += v[j].x * v[j].x + v[j].y * v[j].y + v[j].z * v[j].z + v[j].w * v[j].w;
    }
#pragma unroll
    for (int o = 16; o; o >>= 1) {
        s  += __shfl_xor_sync(0xffffffffu, s,  o);
        s2 += __shfl_xor_sync(0xffffffffu, s2, o);
    }
    float mean = s * (1.0f / D_MODEL);
    float var  = s2 * (1.0f / D_MODEL) - mean * mean;
    float inv  = rsqrtf(var + 1e-5f);
    float4* orow = (float4*)(out + (size_t)warp * D_MODEL);
    __nv_bfloat16* brow = outb + (size_t)warp * D_MODEL;
#pragma unroll
    for (int j = 0; j < 3; j++) {
        int idx = lane + 32 * j;
        float4 g4 = ((const float4*)gain)[idx];
        float4 b4 = ((const float4*)bias)[idx];
        float4 o;
        o.x = (v[j].x - mean) * inv * g4.x + b4.x;
        o.y = (v[j].y - mean) * inv * g4.y + b4.y;
        o.z = (v[j].z - mean) * inv * g4.z + b4.z;
        o.w = (v[j].w - mean) * inv * g4.w + b4.w;
        orow[idx] = o;
        uint2 packed;
        packed.x = packbf(o.x, o.y);
        packed.y = packbf(o.z, o.w);
        *(uint2*)&brow[idx * 4] = packed;
    }
}

// ---------------------------------------------------------------------------
// bf16 HMMA GEMM (R6-proven): 128x128, BK=32, 256 thr, cp.async x2, scalar LDS
// ---------------------------------------------------------------------------
#define BK  32
#define AST 40

template <bool BIAS, bool RES, bool RELU, bool OUTBF>
__global__ __launch_bounds__(256)
void bgemm(const __nv_bfloat16* __restrict__ A, const __nv_bfloat16* __restrict__ Bw,
           const float* __restrict__ bias, const float* __restrict__ Rsd,
           void* __restrict__ Cout, int N, int K) {
    __shared__ __nv_bfloat16 As[2][128 * AST];
    __shared__ __nv_bfloat16 Bs[2][128 * AST];

    const int tid = threadIdx.x;
    const int lane = tid & 31, warp = tid >> 5;
    const int warp_m = warp & 1, warp_n = warp >> 1;
    const int g = lane >> 2, tg = lane & 3;
    const int bm = blockIdx.y * 128, bn = blockIdx.x * 128;

    const uint32_t sA[2] = { smem_u32(As[0]), smem_u32(As[1]) };
    const uint32_t sB[2] = { smem_u32(Bs[0]), smem_u32(Bs[1]) };

    auto issue = [&](int k0, int buf) {
#pragma unroll
        for (int i = 0; i < 2; i++) {
            int idx = tid + i * 256;
            int row = idx >> 2, seg = idx & 3;
            cp16(sA[buf] + (row * AST + seg * 8) * 2,
                 A + (size_t)(bm + row) * K + k0 + seg * 8);
        }
#pragma unroll
        for (int i = 0; i < 2; i++) {
            int idx = tid + i * 256;
            int row = idx >> 2, seg = idx & 3;
            cp16(sB[buf] + (row * AST + seg * 8) * 2,
                 Bw + (size_t)(bn + row) * K + k0 + seg * 8);
        }
        asm volatile("cp.async.commit_group;" ::: "memory");
    };

    float acc[4][4][4] = {};

    issue(0, 0);
    const int NC = K / BK;
    for (int c = 0; c < NC; c++) {
        const int buf = c & 1;
        if (c + 1 < NC) {
            issue((c + 1) * BK, buf ^ 1);
            asm volatile("cp.async.wait_group 1;" ::: "memory");
        } else {
            asm volatile("cp.async.wait_group 0;" ::: "memory");
        }
        __syncthreads();

        const __nv_bfloat16* as = As[buf];
        const __nv_bfloat16* bs = Bs[buf];
#pragma unroll
        for (int ks = 0; ks < BK; ks += 16) {
            uint32_t afr[4][4], bfr[4][2];
#pragma unroll
            for (int mt = 0; mt < 4; mt++) {
                int m0 = warp_m * 64 + mt * 16 + g;
                afr[mt][0] = *(const uint32_t*)&as[m0 * AST + ks + tg * 2];
                afr[mt][1] = *(const uint32_t*)&as[(m0 + 8) * AST + ks + tg * 2];
                afr[mt][2] = *(const uint32_t*)&as[m0 * AST + ks + 8 + tg * 2];
                afr[mt][3] = *(const uint32_t*)&as[(m0 + 8) * AST + ks + 8 + tg * 2];
            }
#pragma unroll
            for (int nt = 0; nt < 4; nt++) {
                int n0 = warp_n * 32 + nt * 8 + g;
                bfr[nt][0] = *(const uint32_t*)&bs[n0 * AST + ks + tg * 2];
                bfr[nt][1] = *(const uint32_t*)&bs[n0 * AST + ks + 8 + tg * 2];
            }
#pragma unroll
            for (int mt = 0; mt < 4; mt++)
#pragma unroll
                for (int nt = 0; nt < 4; nt++)
                    mma_bf16(acc[mt][nt], afr[mt], bfr[nt]);
        }
        __syncthreads();
    }

    float* Cf = (float*)Cout;
    __nv_bfloat16* Cb = (__nv_bfloat16*)Cout;
#pragma unroll
    for (int mt = 0; mt < 4; mt++) {
#pragma unroll
        for (int half = 0; half < 2; half++) {
            int row = bm + warp_m * 64 + mt * 16 + g + half * 8;
#pragma unroll
            for (int nt = 0; nt < 4; nt++) {
                int col = bn + warp_n * 32 + nt * 8 + tg * 2;
                float vx = acc[mt][nt][half * 2 + 0];
                float vy = acc[mt][nt][half * 2 + 1];
                if (BIAS) {
                    float2 b2 = *(const float2*)&bias[col];
                    vx += b2.x; vy += b2.y;
                }
                if (RELU) { vx = fmaxf(vx, 0.f); vy = fmaxf(vy, 0.f); }
                if (RES) {
                    float2 r2 = *(const float2*)&Rsd[(size_t)row * N + col];
                    vx += r2.x; vy += r2.y;
                }
                if (OUTBF) {
                    *(uint32_t*)&Cb[(size_t)row * N + col] = packbf(vx, vy);
                } else {
                    *(float2*)&Cf[(size_t)row * N + col] = make_float2(vx, vy);
                }
            }
        }
    }
}

// ---------------------------------------------------------------------------
// Fused O-projection + residual + LayerNorm2:
//   res = attnb @ WoT^T + bo + h1 ;  h2 = LN(res, g2, be2) ; h2b = bf16(h2)
// One CTA owns a full 128x384 row-block. 512 threads (16 warps, 4x4 grid,
// warp tile 32x96). Mainloop double-buffered cp.async; epilogue stages res
// in smem (fp32) then does per-row LN.
// ---------------------------------------------------------------------------
#define OK_DIM  384
#define CT_ST   388   // fp32 row stride for res tile in smem (mod 32 = 4)
#define OP_AS_BYTES (2 * 128 * AST * 2)              // 20480
#define OP_BS_BYTES (2 * OK_DIM * AST * 2)           // 61440
#define OP_SMEM_MAIN (OP_AS_BYTES + OP_BS_BYTES)     // 81920
#define OP_SMEM_TOTAL (128 * CT_ST * 4)              // 198656 (overlaps mainloop bufs)

__global__ __launch_bounds__(512)
void oproj_ln_kernel(const __nv_bfloat16* __restrict__ A,   // attnb [M,384]
                     const __nv_bfloat16* __restrict__ Bw,  // WoT [384][384]
                     const float* __restrict__ bo,
                     const float* __restrict__ h1,
                     const float* __restrict__ gain,
                     const float* __restrict__ beta,
                     float* __restrict__ h2,
                     __nv_bfloat16* __restrict__ h2b) {
    extern __shared__ char smem[];
    __nv_bfloat16* As = (__nv_bfloat16*)smem;
    __nv_bfloat16* Bs = (__nv_bfloat16*)(smem + OP_AS_BYTES);
    float* Ct = (float*)smem;

    const int tid = threadIdx.x;
    const int lane = tid & 31, warp = tid >> 5;
    const int warp_m = warp & 3;     // 4 groups of 32 rows
    const int warp_n = warp >> 2;    // 4 groups of 96 cols
    const int g = lane >> 2, tg = lane & 3;
    const int bm = blockIdx.x * 128;

    const uint32_t sA = smem_u32(As);
    const uint32_t sB = smem_u32(Bs);

    auto issue = [&](int k0, int buf) {
        {
            int row = tid >> 2, seg = tid & 3;
            cp16(sA + (buf * 128 * AST + row * AST + seg * 8) * 2,
                 A + (size_t)(bm + row) * OK_DIM + k0 + seg * 8);
        }
#pragma unroll
        for (int i = 0; i < 3; i++) {
            int idx = tid + i * 512;
            int row = idx >> 2, seg = idx & 3;
            cp16(sB + (buf * OK_DIM * AST + row * AST + seg * 8) * 2,
                 Bw + (size_t)row * OK_DIM + k0 + seg * 8);
        }
        asm volatile("cp.async.commit_group;" ::: "memory");
    };

    float acc[2][12][4] = {};

    issue(0, 0);
    const int NC = OK_DIM / BK;   // 12
    for (int c = 0; c < NC; c++) {
        const int buf = c & 1;
        if (c + 1 < NC) {
            issue((c + 1) * BK, buf ^ 1);
            asm volatile("cp.async.wait_group 1;" ::: "memory");
        } else {
            asm volatile("cp.async.wait_group 0;" ::: "memory");
        }
        __syncthreads();

        const __nv_bfloat16* as = As + buf * 128 * AST;
        const __nv_bfloat16* bs = Bs + buf * OK_DIM * AST;
#pragma unroll
        for (int ks = 0; ks < BK; ks += 16) {
            uint32_t afr[2][4];
#pragma unroll
            for (int mt = 0; mt < 2; mt++) {
                int m0 = warp_m * 32 + mt * 16 + g;
                afr[mt][0] = *(const uint32_t*)&as[m0 * AST + ks + tg * 2];
                afr[mt][1] = *(const uint32_t*)&as[(m0 + 8) * AST + ks + tg * 2];
                afr[mt][2] = *(const uint32_t*)&as[m0 * AST + ks + 8 + tg * 2];
                afr[mt][3] = *(const uint32_t*)&as[(m0 + 8) * AST + ks + 8 + tg * 2];
            }
#pragma unroll
            for (int nt = 0; nt < 12; nt++) {
                int n0 = warp_n * 96 + nt * 8 + g;
                uint32_t bfr[2];
                bfr[0] = *(const uint32_t*)&bs[n0 * AST + ks + tg * 2];
                bfr[1] = *(const uint32_t*)&bs[n0 * AST + ks + 8 + tg * 2];
                mma_bf16(acc[0][nt], afr[0], bfr);
                mma_bf16(acc[1][nt], afr[1], bfr);
            }
        }
        __syncthreads();
    }

    // ---- stage res = acc + bo + h1 into smem (fp32) ----
#pragma unroll
    for (int mt = 0; mt < 2; mt++) {
#pragma unroll
        for (int half = 0; half < 2; half++) {
            int rl = warp_m * 32 + mt * 16 + g + half * 8;
            const float* h1row = h1 + (size_t)(bm + rl) * D_MODEL;
#pragma unroll
            for (int nt = 0; nt < 12; nt++) {
                int col = warp_n * 96 + nt * 8 + tg * 2;
                float2 b2 = *(const float2*)&bo[col];
                float2 r2 = *(const float2*)&h1row[col];
                Ct[rl * CT_ST + col]     = acc[mt][nt][half * 2 + 0] + b2.x + r2.x;
                Ct[rl * CT_ST + col + 1] = acc[mt][nt][half * 2 + 1] + b2.y + r2.y;
            }
        }
    }
    __syncthreads();

    // ---- per-row LayerNorm: warp w handles rows w, w+16, ... ----
    float gc[12], bc[12];
#pragma unroll
    for (int j = 0; j < 12; j++) {
        gc[j] = gain[lane + 32 * j];
        bc[j] = beta[lane + 32 * j];
    }
    for (int r = warp; r < 128; r += 16) {
        float vals[12];
        float s = 0.f, s2 = 0.f;
#pragma unroll
        for (int j = 0; j < 12; j++) {
            float v = Ct[r * CT_ST + lane + 32 * j];
            vals[j] = v;
            s += v; s2 += v * v;
        }
#pragma unroll
        for (int o = 16; o; o >>= 1) {
            s  += __shfl_xor_sync(0xffffffffu, s,  o);
            s2 += __shfl_xor_sync(0xffffffffu, s2, o);
        }
        float mean = s * (1.0f / D_MODEL);
        float var  = s2 * (1.0f / D_MODEL) - mean * mean;
        float inv  = rsqrtf(var + 1e-5f);
        float* orow = h2 + (size_t)(bm + r) * D_MODEL;
        __nv_bfloat16* brow = h2b + (size_t)(bm + r) * D_MODEL;
#pragma unroll
        for (int j = 0; j < 12; j++) {
            float o = (vals[j] - mean) * inv * gc[j] + bc[j];
            orow[lane + 32 * j] = o;
            brow[lane + 32 * j] = __float2bfloat16(o);
        }
    }
}

// ---------------------------------------------------------------------------
// Tensor-core causal attention (unchanged from R6)
// ---------------------------------------------------------------------------
__global__ __launch_bounds__(128) void attn_kernel(__nv_bfloat16* __restrict__ out) {
    const int bh = blockIdx.x;
    const int b = bh >> 3, h = bh & 7;
    const float* qkv = g_big;

    __shared__ float qs[T_SEQ][52];
    __shared__ float ksm[T_SEQ][52];
    __shared__ __nv_bfloat16 vt[HS][72];

    const int tid = threadIdx.x;
    const int lane = tid & 31, warp = tid >> 5;
    const int g = lane >> 2, tg = lane & 3;

    for (int i = tid; i < T_SEQ * 12; i += 128) {
        int r = i / 12, c4 = (i % 12) * 4;
        size_t base = (size_t)(b * T_SEQ + r) * QKV_N + h * HS + c4;
        *(float4*)&qs[r][c4]  = *(const float4*)&qkv[base];
        *(float4*)&ksm[r][c4] = *(const float4*)&qkv[base + D_MODEL];
        float4 v4 = *(const float4*)&qkv[base + 2 * D_MODEL];
        vt[c4 + 0][r] = __float2bfloat16(v4.x);
        vt[c4 + 1][r] = __float2bfloat16(v4.y);
        vt[c4 + 2][r] = __float2bfloat16(v4.z);
        vt[c4 + 3][r] = __float2bfloat16(v4.w);
    }
    __syncthreads();

    const int m0 = warp * 16;

    float sacc[8][4] = {};
#pragma unroll
    for (int ks = 0; ks < HS; ks += 8) {
        uint32_t a[4];
        a[0] = f2tf32(qs[m0 + g][ks + tg]);
        a[1] = f2tf32(qs[m0 + g + 8][ks + tg]);
        a[2] = f2tf32(qs[m0 + g][ks + tg + 4]);
        a[3] = f2tf32(qs[m0 + g + 8][ks + tg + 4]);
#pragma unroll
        for (int nt = 0; nt < 8; nt++) {
            uint32_t bf[2];
            bf[0] = f2tf32(ksm[nt * 8 + g][ks + tg]);
            bf[1] = f2tf32(ksm[nt * 8 + g][ks + tg + 4]);
            mma_tf32(sacc[nt], a, bf);
        }
    }

    const float scale = 0.14433756729740643f;
    const int row0 = m0 + g, row1 = m0 + g + 8;
    float mx0 = -1e30f, mx1 = -1e30f;
#pragma unroll
    for (int nt = 0; nt < 8; nt++) {
#pragma unroll
        for (int j = 0; j < 2; j++) {
            int col = nt * 8 + tg * 2 + j;
            float s0 = sacc[nt][j] * scale;
            float s1 = sacc[nt][2 + j] * scale;
            if (col > row0) s0 = -1e30f;
            if (col > row1) s1 = -1e30f;
            sacc[nt][j] = s0;     sacc[nt][2 + j] = s1;
            mx0 = fmaxf(mx0, s0); mx1 = fmaxf(mx1, s1);
        }
    }
    mx0 = fmaxf(mx0, __shfl_xor_sync(0xffffffffu, mx0, 1));
    mx0 = fmaxf(mx0, __shfl_xor_sync(0xffffffffu, mx0, 2));
    mx1 = fmaxf(mx1, __shfl_xor_sync(0xffffffffu, mx1, 1));
    mx1 = fmaxf(mx1, __shfl_xor_sync(0xffffffffu, mx1, 2));

    float sum0 = 0.f, sum1 = 0.f;
#pragma unroll
    for (int nt = 0; nt < 8; nt++) {
#pragma unroll
        for (int j = 0; j < 2; j++) {
            float e0 = __expf(sacc[nt][j] - mx0);
            float e1 = __expf(sacc[nt][2 + j] - mx1);
            sacc[nt][j] = e0;     sacc[nt][2 + j] = e1;
            sum0 += e0;           sum1 += e1;
        }
    }
    sum0 += __shfl_xor_sync(0xffffffffu, sum0, 1);
    sum0 += __shfl_xor_sync(0xffffffffu, sum0, 2);
    sum1 += __shfl_xor_sync(0xffffffffu, sum1, 1);
    sum1 += __shfl_xor_sync(0xffffffffu, sum1, 2);
    const float inv0 = 1.0f / sum0, inv1 = 1.0f / sum1;

    float o[6][4] = {};
#pragma unroll
    for (int ks = 0; ks < 4; ks++) {
        uint32_t a[4];
        a[0] = packbf(sacc[2 * ks][0],     sacc[2 * ks][1]);
        a[1] = packbf(sacc[2 * ks][2],     sacc[2 * ks][3]);
        a[2] = packbf(sacc[2 * ks + 1][0], sacc[2 * ks + 1][1]);
        a[3] = packbf(sacc[2 * ks + 1][2], sacc[2 * ks + 1][3]);
#pragma unroll
        for (int nt = 0; nt < 6; nt++) {
            uint32_t bf[2];
            bf[0] = *(const uint32_t*)&vt[nt * 8 + g][ks * 16 + tg * 2];
            bf[1] = *(const uint32_t*)&vt[nt * 8 + g][ks * 16 + 8 + tg * 2];
            mma_bf16(o[nt], a, bf);
        }
    }

    const size_t ob0 = (size_t)(b * T_SEQ + row0) * D_MODEL + h * HS;
    const size_t ob1 = (size_t)(b * T_SEQ + row1) * D_MODEL + h * HS;
#pragma unroll
    for (int nt = 0; nt < 6; nt++) {
        int col = nt * 8 + tg * 2;
        *(uint32_t*)&out[ob0 + col] = packbf(o[nt][0] * inv0, o[nt][1] * inv0);
        *(uint32_t*)&out[ob1 + col] = packbf(o[nt][2] * inv1, o[nt][3] * inv1);
    }
}

// ---------------------------------------------------------------------------
// Launcher
// ---------------------------------------------------------------------------
extern "C" void kernel_launch(void* const* d_in, const int* in_sizes, int n_in,
                              void* d_out, int out_size) {
    (void)in_sizes; (void)n_in; (void)out_size;
    const float* x  = (const float*)d_in[0];
    const float* wq = (const float*)d_in[1];
    const float* bq = (const float*)d_in[2];
    const float* wk = (const float*)d_in[3];
    const float* bk = (const float*)d_in[4];
    const float* wv = (const float*)d_in[5];
    const float* bv = (const float*)d_in[6];
    const float* wo = (const float*)d_in[7];
    const float* bo = (const float*)d_in[8];
    const float* w1 = (const float*)d_in[9];
    const float* b1 = (const float*)d_in[10];
    const float* w2 = (const float*)d_in[11];
    const float* b2 = (const float*)d_in[12];
    const float* g1 = (const float*)d_in[13];
    const float* be1 = (const float*)d_in[14];
    const float* g2 = (const float*)d_in[15];
    const float* be2 = (const float*)d_in[16];
    float* out = (float*)d_out;

    float *p_h1, *p_h2, *p_big, *p_bqkv;
    __nv_bfloat16 *p_h1b, *p_h2b, *p_attnb, *p_midb, *p_WqkvT, *p_WoT, *p_W1T, *p_W2T;
    cudaGetSymbolAddress((void**)&p_h1, g_h1);
    cudaGetSymbolAddress((void**)&p_h1b, g_h1b);
    cudaGetSymbolAddress((void**)&p_h2, g_h2);
    cudaGetSymbolAddress((void**)&p_h2b, g_h2b);
    cudaGetSymbolAddress((void**)&p_big, g_big);
    cudaGetSymbolAddress((void**)&p_attnb, g_attnb);
    cudaGetSymbolAddress((void**)&p_midb, g_midb);
    cudaGetSymbolAddress((void**)&p_WqkvT, g_WqkvT);
    cudaGetSymbolAddress((void**)&p_bqkv, g_bqkv);
    cudaGetSymbolAddress((void**)&p_WoT, g_WoT);
    cudaGetSymbolAddress((void**)&p_W1T, g_W1T);
    cudaGetSymbolAddress((void**)&p_W2T, g_W2T);

    cudaFuncSetAttribute(oproj_ln_kernel,
                         cudaFuncAttributeMaxDynamicSharedMemorySize, OP_SMEM_TOTAL);

    // 0. weight repacks -> bf16 [N][K]
    pack_qkvT_kernel<<<(QKV_N * D_MODEL + 255) / 256, 256>>>(wq, wk, wv, bq, bk, bv);
    transpose_bf_kernel<<<(D_MODEL * D_MODEL + 255) / 256, 256>>>(wo, p_WoT, D_MODEL, D_MODEL);
    transpose_bf_kernel<<<(D_MODEL * D_FF + 255) / 256, 256>>>(w1, p_W1T, D_MODEL, D_FF);
    transpose_bf_kernel<<<(D_FF * D_MODEL + 255) / 256, 256>>>(w2, p_W2T, D_FF, D_MODEL);

    // 1. LN1: x -> h1 (fp32) + h1b (bf16)
    ln_kernel<<<(M_TOK * 32) / 256, 256>>>(x, g1, be1, p_h1, p_h1b);

    // 2. QKV GEMM: h1b @ WqkvT^T + bqkv -> g_big (fp32)
    bgemm<true, false, false, false><<<dim3(QKV_N / 128, M_TOK / 128), 256>>>(
        p_h1b, p_WqkvT, p_bqkv, nullptr, p_big, QKV_N, D_MODEL);

    // 3. attention (tensor-core) -> attnb (bf16)
    attn_kernel<<<BATCH * NH, 128>>>(p_attnb);

    // 4. fused O-proj + residual + LN2 -> h2 (fp32) + h2b (bf16)
    oproj_ln_kernel<<<M_TOK / 128, 512, OP_SMEM_TOTAL>>>(
        p_attnb, p_WoT, bo, p_h1, g2, be2, p_h2, p_h2b);

    // 5. FF1 + ReLU: h2b @ W1T^T + b1 -> midb (bf16)
    bgemm<true, false, true, true><<<dim3(D_FF / 128, M_TOK / 128), 256>>>(
        p_h2b, p_W1T, b1, nullptr, p_midb, D_FF, D_MODEL);

    // 6. FF2 + bias + residual: midb @ W2T^T + b2 + h2 -> out (fp32)
    bgemm<true, true, false, false><<<dim3(D_MODEL / 128, M_TOK / 128), 256>>>(
        p_midb, p_W2T, b2, p_h2, out, D_MODEL, D_FF);
}

// round 13
// speedup vs baseline: 1.0647x; 1.0027x over previous
#include <cuda_runtime.h>
#include <cuda_bf16.h>
#include <math.h>
#include <stdint.h>

// ---------------------------------------------------------------------------
// Problem constants
// ---------------------------------------------------------------------------
#define BATCH   2048
#define T_SEQ   64
#define D_MODEL 384
#define NH      8
#define HS      48
#define D_FF    1536
#define M_TOK   (BATCH * T_SEQ)          // 131072
#define QKV_N   (3 * D_MODEL)            // 1152

// ---------------------------------------------------------------------------
// Scratch (static device globals)
// ---------------------------------------------------------------------------
__device__ float          g_h1  [(size_t)M_TOK * D_MODEL];
__device__ __nv_bfloat16  g_h1b [(size_t)M_TOK * D_MODEL];
__device__ float          g_h2  [(size_t)M_TOK * D_MODEL];
__device__ __nv_bfloat16  g_h2b [(size_t)M_TOK * D_MODEL];
__device__ float          g_big [(size_t)M_TOK * QKV_N];    // Q,K fp32 (V unused)
__device__ __nv_bfloat16  g_vb  [(size_t)M_TOK * D_MODEL];  // V bf16
__device__ __nv_bfloat16  g_attnb[(size_t)M_TOK * D_MODEL]; // attn out bf16
__device__ __nv_bfloat16  g_midb[(size_t)M_TOK * D_FF];     // FF mid bf16
__device__ __nv_bfloat16  g_WqkvT[(size_t)QKV_N * D_MODEL]; // [1152][384] bf16
__device__ float          g_bqkv [QKV_N];
__device__ __nv_bfloat16  g_WoT  [(size_t)D_MODEL * D_MODEL];
__device__ __nv_bfloat16  g_W1T  [(size_t)D_FF * D_MODEL];
__device__ __nv_bfloat16  g_W2T  [(size_t)D_MODEL * D_FF];

// ---------------------------------------------------------------------------
// Helpers
// ---------------------------------------------------------------------------
__device__ __forceinline__ uint32_t smem_u32(const void* p) {
    uint32_t a;
    asm("{ .reg .u64 t; cvta.to.shared.u64 t, %1; cvt.u32.u64 %0, t; }" : "=r"(a) : "l"(p));
    return a;
}
__device__ __forceinline__ void cp16(uint32_t dst, const void* src) {
    asm volatile("cp.async.cg.shared.global [%0], [%1], 16;" :: "r"(dst), "l"(src));
}
__device__ __forceinline__ void mma_bf16(float* c, const uint32_t* a, const uint32_t* b) {
    asm volatile(
        "mma.sync.aligned.m16n8k16.row.col.f32.bf16.bf16.f32 "
        "{%0,%1,%2,%3}, {%4,%5,%6,%7}, {%8,%9}, {%0,%1,%2,%3};"
        : "+f"(c[0]), "+f"(c[1]), "+f"(c[2]), "+f"(c[3])
        : "r"(a[0]), "r"(a[1]), "r"(a[2]), "r"(a[3]), "r"(b[0]), "r"(b[1]));
}
__device__ __forceinline__ void mma_tf32(float* c, const uint32_t* a, const uint32_t* b) {
    asm volatile(
        "mma.sync.aligned.m16n8k8.row.col.f32.tf32.tf32.f32 "
        "{%0,%1,%2,%3}, {%4,%5,%6,%7}, {%8,%9}, {%0,%1,%2,%3};"
        : "+f"(c[0]), "+f"(c[1]), "+f"(c[2]), "+f"(c[3])
        : "r"(a[0]), "r"(a[1]), "r"(a[2]), "r"(a[3]), "r"(b[0]), "r"(b[1]));
}
__device__ __forceinline__ uint32_t f2tf32(float f) {
    uint32_t u;
    asm("cvt.rna.tf32.f32 %0, %1;" : "=r"(u) : "f"(f));
    return u;
}
__device__ __forceinline__ uint32_t packbf(float x, float y) {
    __nv_bfloat162 p = __floats2bfloat162_rn(x, y);
    return *(uint32_t*)&p;
}

// ---------------------------------------------------------------------------
// Weight repack kernels (fp32 -> bf16, transposed to [N][K] K-major)
// ---------------------------------------------------------------------------
__global__ void pack_qkvT_kernel(const float* __restrict__ wq, const float* __restrict__ wk,
                                 const float* __restrict__ wv, const float* __restrict__ bq,
                                 const float* __restrict__ bk, const float* __restrict__ bv) {
    int i = blockIdx.x * blockDim.x + threadIdx.x;
    const int total = QKV_N * D_MODEL;
    if (i < total) {
        int col = i / D_MODEL;
        int d   = i % D_MODEL;
        int which = col / D_MODEL;
        int hc    = col % D_MODEL;
        int h = hc / HS, e = hc % HS;
        const float* w = (which == 0) ? wq : (which == 1) ? wk : wv;
        g_WqkvT[i] = __float2bfloat16(w[((size_t)h * D_MODEL + d) * HS + e]);
    }
    if (i < QKV_N) {
        int which = i / D_MODEL;
        int hc    = i % D_MODEL;
        int h = hc / HS, e = hc % HS;
        const float* bsrc = (which == 0) ? bq : (which == 1) ? bk : bv;
        g_bqkv[i] = bsrc[h * HS + e];
    }
}

// Merged transpose of wo, w1, w2 -> bf16 [N][K]
#define WO_ELEMS (D_MODEL * D_MODEL)     // 147456
#define W1_ELEMS (D_FF * D_MODEL)        // 589824
#define W2_ELEMS (D_MODEL * D_FF)        // 589824
#define TR_TOTAL (WO_ELEMS + W1_ELEMS + W2_ELEMS)

__global__ void transpose_all_kernel(const float* __restrict__ wo, const float* __restrict__ w1,
                                     const float* __restrict__ w2) {
    int i = blockIdx.x * blockDim.x + threadIdx.x;
    if (i < WO_ELEMS) {
        int n = i / D_MODEL, k = i % D_MODEL;
        g_WoT[i] = __float2bfloat16(wo[(size_t)k * D_MODEL + n]);
    } else if (i < WO_ELEMS + W1_ELEMS) {
        int j = i - WO_ELEMS;
        int n = j / D_MODEL, k = j % D_MODEL;
        g_W1T[j] = __float2bfloat16(w1[(size_t)k * D_FF + n]);
    } else if (i < TR_TOTAL) {
        int j = i - WO_ELEMS - W1_ELEMS;
        int n = j / D_FF, k = j % D_FF;
        g_W2T[j] = __float2bfloat16(w2[(size_t)k * D_MODEL + n]);
    }
}

// ---------------------------------------------------------------------------
// LayerNorm: one warp per token row; writes fp32 AND bf16 outputs
// ---------------------------------------------------------------------------
__global__ void ln_kernel(const float* __restrict__ in, const float* __restrict__ gain,
                          const float* __restrict__ bias, float* __restrict__ out,
                          __nv_bfloat16* __restrict__ outb) {
    int warp = (blockIdx.x * blockDim.x + threadIdx.x) >> 5;
    int lane = threadIdx.x & 31;
    if (warp >= M_TOK) return;
    const float4* row = (const float4*)(in + (size_t)warp * D_MODEL);
    float4 v[3];
    float s = 0.f, s2 = 0.f;
#pragma unroll
    for (int j = 0; j < 3; j++) {
        v[j] = row[lane + 32 * j];
        s  += v[j].x + v[j].y + v[j].z + v[j].w;
        s2 += v[j].x * v[j].x + v[j].y * v[j].y + v[j].z * v[j].z + v[j].w * v[j].w;
    }
#pragma unroll
    for (int o = 16; o; o >>= 1) {
        s  += __shfl_xor_sync(0xffffffffu, s,  o);
        s2 += __shfl_xor_sync(0xffffffffu, s2, o);
    }
    float mean = s * (1.0f / D_MODEL);
    float var  = s2 * (1.0f / D_MODEL) - mean * mean;
    float inv  = rsqrtf(var + 1e-5f);
    float4* orow = (float4*)(out + (size_t)warp * D_MODEL);
    __nv_bfloat16* brow = outb + (size_t)warp * D_MODEL;
#pragma unroll
    for (int j = 0; j < 3; j++) {
        int idx = lane + 32 * j;
        float4 g4 = ((const float4*)gain)[idx];
        float4 b4 = ((const float4*)bias)[idx];
        float4 o;
        o.x = (v[j].x - mean) * inv * g4.x + b4.x;
        o.y = (v[j].y - mean) * inv * g4.y + b4.y;
        o.z = (v[j].z - mean) * inv * g4.z + b4.z;
        o.w = (v[j].w - mean) * inv * g4.w + b4.w;
        orow[idx] = o;
        uint2 packed;
        packed.x = packbf(o.x, o.y);
        packed.y = packbf(o.z, o.w);
        *(uint2*)&brow[idx * 4] = packed;
    }
}

// ---------------------------------------------------------------------------
// bf16 HMMA GEMM: 128x128, BK=32, 256 thr, 3-stage cp.async, scalar LDS frags.
// QKVOUT: columns >= 768 (whole CTAs) are V -> stored bf16 to Vout[., 384].
// ---------------------------------------------------------------------------
#define BK  32
#define AST 40
#define BG_BUF   (128 * AST * 2)          // 10240 bytes per buffer
#define BG_SMEM  (6 * BG_BUF)             // 3 A bufs + 3 B bufs = 61440

template <bool BIAS, bool RES, bool RELU, bool OUTBF, bool QKVOUT>
__global__ __launch_bounds__(256)
void bgemm(const __nv_bfloat16* __restrict__ A, const __nv_bfloat16* __restrict__ Bw,
           const float* __restrict__ bias, const float* __restrict__ Rsd,
           void* __restrict__ Cout, __nv_bfloat16* __restrict__ Vout, int N, int K) {
    extern __shared__ char dsm[];
    const uint32_t sAb = smem_u32(dsm);
    const uint32_t sBb = sAb + 3 * BG_BUF;

    const int tid = threadIdx.x;
    const int lane = tid & 31, warp = tid >> 5;
    const int warp_m = warp & 1, warp_n = warp >> 1;
    const int g = lane >> 2, tg = lane & 3;
    const int bm = blockIdx.y * 128, bn = blockIdx.x * 128;

    auto issue = [&](int k0, int buf) {
#pragma unroll
        for (int i = 0; i < 2; i++) {
            int idx = tid + i * 256;
            int row = idx >> 2, seg = idx & 3;
            cp16(sAb + buf * BG_BUF + (row * AST + seg * 8) * 2,
                 A + (size_t)(bm + row) * K + k0 + seg * 8);
        }
#pragma unroll
        for (int i = 0; i < 2; i++) {
            int idx = tid + i * 256;
            int row = idx >> 2, seg = idx & 3;
            cp16(sBb + buf * BG_BUF + (row * AST + seg * 8) * 2,
                 Bw + (size_t)(bn + row) * K + k0 + seg * 8);
        }
        asm volatile("cp.async.commit_group;" ::: "memory");
    };

    float acc[4][4][4] = {};

    const int NC = K / BK;
    issue(0, 0);
    issue(BK, 1);
    for (int c = 0; c < NC; c++) {
        const int buf = c % 3;
        if (c + 2 < NC) {
            issue((c + 2) * BK, (c + 2) % 3);
            asm volatile("cp.async.wait_group 2;" ::: "memory");
        } else if (c + 1 < NC) {
            asm volatile("cp.async.wait_group 1;" ::: "memory");
        } else {
            asm volatile("cp.async.wait_group 0;" ::: "memory");
        }
        __syncthreads();

        const __nv_bfloat16* as = (const __nv_bfloat16*)(dsm) + buf * 128 * AST;
        const __nv_bfloat16* bs = (const __nv_bfloat16*)(dsm + 3 * BG_BUF) + buf * 128 * AST;
#pragma unroll
        for (int ks = 0; ks < BK; ks += 16) {
            uint32_t afr[4][4], bfr[4][2];
#pragma unroll
            for (int mt = 0; mt < 4; mt++) {
                int m0 = warp_m * 64 + mt * 16 + g;
                afr[mt][0] = *(const uint32_t*)&as[m0 * AST + ks + tg * 2];
                afr[mt][1] = *(const uint32_t*)&as[(m0 + 8) * AST + ks + tg * 2];
                afr[mt][2] = *(const uint32_t*)&as[m0 * AST + ks + 8 + tg * 2];
                afr[mt][3] = *(const uint32_t*)&as[(m0 + 8) * AST + ks + 8 + tg * 2];
            }
#pragma unroll
            for (int nt = 0; nt < 4; nt++) {
                int n0 = warp_n * 32 + nt * 8 + g;
                bfr[nt][0] = *(const uint32_t*)&bs[n0 * AST + ks + tg * 2];
                bfr[nt][1] = *(const uint32_t*)&bs[n0 * AST + ks + 8 + tg * 2];
            }
#pragma unroll
            for (int mt = 0; mt < 4; mt++)
#pragma unroll
                for (int nt = 0; nt < 4; nt++)
                    mma_bf16(acc[mt][nt], afr[mt], bfr[nt]);
        }
        __syncthreads();
    }

    float* Cf = (float*)Cout;
    __nv_bfloat16* Cb = (__nv_bfloat16*)Cout;
    const bool vregion = QKVOUT && (bn >= 2 * D_MODEL);
#pragma unroll
    for (int mt = 0; mt < 4; mt++) {
#pragma unroll
        for (int half = 0; half < 2; half++) {
            int row = bm + warp_m * 64 + mt * 16 + g + half * 8;
#pragma unroll
            for (int nt = 0; nt < 4; nt++) {
                int col = bn + warp_n * 32 + nt * 8 + tg * 2;
                float vx = acc[mt][nt][half * 2 + 0];
                float vy = acc[mt][nt][half * 2 + 1];
                if (BIAS) {
                    float2 b2 = *(const float2*)&bias[col];
                    vx += b2.x; vy += b2.y;
                }
                if (RELU) { vx = fmaxf(vx, 0.f); vy = fmaxf(vy, 0.f); }
                if (RES) {
                    float2 r2 = *(const float2*)&Rsd[(size_t)row * N + col];
                    vx += r2.x; vy += r2.y;
                }
                if (QKVOUT) {
                    if (vregion) {
                        *(uint32_t*)&Vout[(size_t)row * D_MODEL + (col - 2 * D_MODEL)] =
                            packbf(vx, vy);
                    } else {
                        *(float2*)&Cf[(size_t)row * N + col] = make_float2(vx, vy);
                    }
                } else if (OUTBF) {
                    *(uint32_t*)&Cb[(size_t)row * N + col] = packbf(vx, vy);
                } else {
                    *(float2*)&Cf[(size_t)row * N + col] = make_float2(vx, vy);
                }
            }
        }
    }
}

// ---------------------------------------------------------------------------
// Fused O-projection + residual + LayerNorm2 (R8-proven)
// ---------------------------------------------------------------------------
#define OK_DIM  384
#define CT_ST   388
#define OP_AS_BYTES (2 * 128 * AST * 2)
#define OP_BS_BYTES (2 * OK_DIM * AST * 2)
#define OP_SMEM_TOTAL (128 * CT_ST * 4)

__global__ __launch_bounds__(512)
void oproj_ln_kernel(const __nv_bfloat16* __restrict__ A,
                     const __nv_bfloat16* __restrict__ Bw,
                     const float* __restrict__ bo,
                     const float* __restrict__ h1,
                     const float* __restrict__ gain,
                     const float* __restrict__ beta,
                     float* __restrict__ h2,
                     __nv_bfloat16* __restrict__ h2b) {
    extern __shared__ char smem[];
    __nv_bfloat16* As = (__nv_bfloat16*)smem;
    __nv_bfloat16* Bs = (__nv_bfloat16*)(smem + OP_AS_BYTES);
    float* Ct = (float*)smem;

    const int tid = threadIdx.x;
    const int lane = tid & 31, warp = tid >> 5;
    const int warp_m = warp & 3;
    const int warp_n = warp >> 2;
    const int g = lane >> 2, tg = lane & 3;
    const int bm = blockIdx.x * 128;

    const uint32_t sA = smem_u32(As);
    const uint32_t sB = smem_u32(Bs);

    auto issue = [&](int k0, int buf) {
        {
            int row = tid >> 2, seg = tid & 3;
            cp16(sA + (buf * 128 * AST + row * AST + seg * 8) * 2,
                 A + (size_t)(bm + row) * OK_DIM + k0 + seg * 8);
        }
#pragma unroll
        for (int i = 0; i < 3; i++) {
            int idx = tid + i * 512;
            int row = idx >> 2, seg = idx & 3;
            cp16(sB + (buf * OK_DIM * AST + row * AST + seg * 8) * 2,
                 Bw + (size_t)row * OK_DIM + k0 + seg * 8);
        }
        asm volatile("cp.async.commit_group;" ::: "memory");
    };

    float acc[2][12][4] = {};

    issue(0, 0);
    const int NC = OK_DIM / BK;
    for (int c = 0; c < NC; c++) {
        const int buf = c & 1;
        if (c + 1 < NC) {
            issue((c + 1) * BK, buf ^ 1);
            asm volatile("cp.async.wait_group 1;" ::: "memory");
        } else {
            asm volatile("cp.async.wait_group 0;" ::: "memory");
        }
        __syncthreads();

        const __nv_bfloat16* as = As + buf * 128 * AST;
        const __nv_bfloat16* bs = Bs + buf * OK_DIM * AST;
#pragma unroll
        for (int ks = 0; ks < BK; ks += 16) {
            uint32_t afr[2][4];
#pragma unroll
            for (int mt = 0; mt < 2; mt++) {
                int m0 = warp_m * 32 + mt * 16 + g;
                afr[mt][0] = *(const uint32_t*)&as[m0 * AST + ks + tg * 2];
                afr[mt][1] = *(const uint32_t*)&as[(m0 + 8) * AST + ks + tg * 2];
                afr[mt][2] = *(const uint32_t*)&as[m0 * AST + ks + 8 + tg * 2];
                afr[mt][3] = *(const uint32_t*)&as[(m0 + 8) * AST + ks + 8 + tg * 2];
            }
#pragma unroll
            for (int nt = 0; nt < 12; nt++) {
                int n0 = warp_n * 96 + nt * 8 + g;
                uint32_t bfr[2];
                bfr[0] = *(const uint32_t*)&bs[n0 * AST + ks + tg * 2];
                bfr[1] = *(const uint32_t*)&bs[n0 * AST + ks + 8 + tg * 2];
                mma_bf16(acc[0][nt], afr[0], bfr);
                mma_bf16(acc[1][nt], afr[1], bfr);
            }
        }
        __syncthreads();
    }

#pragma unroll
    for (int mt = 0; mt < 2; mt++) {
#pragma unroll
        for (int half = 0; half < 2; half++) {
            int rl = warp_m * 32 + mt * 16 + g + half * 8;
            const float* h1row = h1 + (size_t)(bm + rl) * D_MODEL;
#pragma unroll
            for (int nt = 0; nt < 12; nt++) {
                int col = warp_n * 96 + nt * 8 + tg * 2;
                float2 b2 = *(const float2*)&bo[col];
                float2 r2 = *(const float2*)&h1row[col];
                Ct[rl * CT_ST + col]     = acc[mt][nt][half * 2 + 0] + b2.x + r2.x;
                Ct[rl * CT_ST + col + 1] = acc[mt][nt][half * 2 + 1] + b2.y + r2.y;
            }
        }
    }
    __syncthreads();

    float gc[12], bc[12];
#pragma unroll
    for (int j = 0; j < 12; j++) {
        gc[j] = gain[lane + 32 * j];
        bc[j] = beta[lane + 32 * j];
    }
    for (int r = warp; r < 128; r += 16) {
        float vals[12];
        float s = 0.f, s2 = 0.f;
#pragma unroll
        for (int j = 0; j < 12; j++) {
            float v = Ct[r * CT_ST + lane + 32 * j];
            vals[j] = v;
            s += v; s2 += v * v;
        }
#pragma unroll
        for (int o = 16; o; o >>= 1) {
            s  += __shfl_xor_sync(0xffffffffu, s,  o);
            s2 += __shfl_xor_sync(0xffffffffu, s2, o);
        }
        float mean = s * (1.0f / D_MODEL);
        float var  = s2 * (1.0f / D_MODEL) - mean * mean;
        float inv  = rsqrtf(var + 1e-5f);
        float* orow = h2 + (size_t)(bm + r) * D_MODEL;
        __nv_bfloat16* brow = h2b + (size_t)(bm + r) * D_MODEL;
#pragma unroll
        for (int j = 0; j < 12; j++) {
            float o = (vals[j] - mean) * inv * gc[j] + bc[j];
            orow[lane + 32 * j] = o;
            brow[lane + 32 * j] = __float2bfloat16(o);
        }
    }
}

// ---------------------------------------------------------------------------
// Tensor-core causal attention; V read as bf16 from g_vb.
// ---------------------------------------------------------------------------
__global__ __launch_bounds__(128) void attn_kernel(__nv_bfloat16* __restrict__ out) {
    const int bh = blockIdx.x;
    const int b = bh >> 3, h = bh & 7;
    const float* qkv = g_big;
    const __nv_bfloat16* vbsrc = g_vb;

    __shared__ float qs[T_SEQ][52];
    __shared__ float ksm[T_SEQ][52];
    __shared__ __nv_bfloat16 vt[HS][72];

    const int tid = threadIdx.x;
    const int lane = tid & 31, warp = tid >> 5;
    const int g = lane >> 2, tg = lane & 3;

    for (int i = tid; i < T_SEQ * 12; i += 128) {
        int r = i / 12, c4 = (i % 12) * 4;
        size_t base = (size_t)(b * T_SEQ + r) * QKV_N + h * HS + c4;
        *(float4*)&qs[r][c4]  = *(const float4*)&qkv[base];
        *(float4*)&ksm[r][c4] = *(const float4*)&qkv[base + D_MODEL];
        uint2 vv = *(const uint2*)&vbsrc[(size_t)(b * T_SEQ + r) * D_MODEL + h * HS + c4];
        __nv_bfloat162 p0 = *(__nv_bfloat162*)&vv.x;
        __nv_bfloat162 p1 = *(__nv_bfloat162*)&vv.y;
        vt[c4 + 0][r] = p0.x;
        vt[c4 + 1][r] = p0.y;
        vt[c4 + 2][r] = p1.x;
        vt[c4 + 3][r] = p1.y;
    }
    __syncthreads();

    const int m0 = warp * 16;

    float sacc[8][4] = {};
#pragma unroll
    for (int ks = 0; ks < HS; ks += 8) {
        uint32_t a[4];
        a[0] = f2tf32(qs[m0 + g][ks + tg]);
        a[1] = f2tf32(qs[m0 + g + 8][ks + tg]);
        a[2] = f2tf32(qs[m0 + g][ks + tg + 4]);
        a[3] = f2tf32(qs[m0 + g + 8][ks + tg + 4]);
#pragma unroll
        for (int nt = 0; nt < 8; nt++) {
            uint32_t bf[2];
            bf[0] = f2tf32(ksm[nt * 8 + g][ks + tg]);
            bf[1] = f2tf32(ksm[nt * 8 + g][ks + tg + 4]);
            mma_tf32(sacc[nt], a, bf);
        }
    }

    const float scale = 0.14433756729740643f;
    const int row0 = m0 + g, row1 = m0 + g + 8;
    float mx0 = -1e30f, mx1 = -1e30f;
#pragma unroll
    for (int nt = 0; nt < 8; nt++) {
#pragma unroll
        for (int j = 0; j < 2; j++) {
            int col = nt * 8 + tg * 2 + j;
            float s0 = sacc[nt][j] * scale;
            float s1 = sacc[nt][2 + j] * scale;
            if (col > row0) s0 = -1e30f;
            if (col > row1) s1 = -1e30f;
            sacc[nt][j] = s0;     sacc[nt][2 + j] = s1;
            mx0 = fmaxf(mx0, s0); mx1 = fmaxf(mx1, s1);
        }
    }
    mx0 = fmaxf(mx0, __shfl_xor_sync(0xffffffffu, mx0, 1));
    mx0 = fmaxf(mx0, __shfl_xor_sync(0xffffffffu, mx0, 2));
    mx1 = fmaxf(mx1, __shfl_xor_sync(0xffffffffu, mx1, 1));
    mx1 = fmaxf(mx1, __shfl_xor_sync(0xffffffffu, mx1, 2));

    float sum0 = 0.f, sum1 = 0.f;
#pragma unroll
    for (int nt = 0; nt < 8; nt++) {
#pragma unroll
        for (int j = 0; j < 2; j++) {
            float e0 = __expf(sacc[nt][j] - mx0);
            float e1 = __expf(sacc[nt][2 + j] - mx1);
            sacc[nt][j] = e0;     sacc[nt][2 + j] = e1;
            sum0 += e0;           sum1 += e1;
        }
    }
    sum0 += __shfl_xor_sync(0xffffffffu, sum0, 1);
    sum0 += __shfl_xor_sync(0xffffffffu, sum0, 2);
    sum1 += __shfl_xor_sync(0xffffffffu, sum1, 1);
    sum1 += __shfl_xor_sync(0xffffffffu, sum1, 2);
    const float inv0 = 1.0f / sum0, inv1 = 1.0f / sum1;

    float o[6][4] = {};
#pragma unroll
    for (int ks = 0; ks < 4; ks++) {
        uint32_t a[4];
        a[0] = packbf(sacc[2 * ks][0],     sacc[2 * ks][1]);
        a[1] = packbf(sacc[2 * ks][2],     sacc[2 * ks][3]);
        a[2] = packbf(sacc[2 * ks + 1][0], sacc[2 * ks + 1][1]);
        a[3] = packbf(sacc[2 * ks + 1][2], sacc[2 * ks + 1][3]);
#pragma unroll
        for (int nt = 0; nt < 6; nt++) {
            uint32_t bf[2];
            bf[0] = *(const uint32_t*)&vt[nt * 8 + g][ks * 16 + tg * 2];
            bf[1] = *(const uint32_t*)&vt[nt * 8 + g][ks * 16 + 8 + tg * 2];
            mma_bf16(o[nt], a, bf);
        }
    }

    const size_t ob0 = (size_t)(b * T_SEQ + row0) * D_MODEL + h * HS;
    const size_t ob1 = (size_t)(b * T_SEQ + row1) * D_MODEL + h * HS;
#pragma unroll
    for (int nt = 0; nt < 6; nt++) {
        int col = nt * 8 + tg * 2;
        *(uint32_t*)&out[ob0 + col] = packbf(o[nt][0] * inv0, o[nt][1] * inv0);
        *(uint32_t*)&out[ob1 + col] = packbf(o[nt][2] * inv1, o[nt][3] * inv1);
    }
}

// ---------------------------------------------------------------------------
// Launcher
// ---------------------------------------------------------------------------
extern "C" void kernel_launch(void* const* d_in, const int* in_sizes, int n_in,
                              void* d_out, int out_size) {
    (void)in_sizes; (void)n_in; (void)out_size;
    const float* x  = (const float*)d_in[0];
    const float* wq = (const float*)d_in[1];
    const float* bq = (const float*)d_in[2];
    const float* wk = (const float*)d_in[3];
    const float* bk = (const float*)d_in[4];
    const float* wv = (const float*)d_in[5];
    const float* bv = (const float*)d_in[6];
    const float* wo = (const float*)d_in[7];
    const float* bo = (const float*)d_in[8];
    const float* w1 = (const float*)d_in[9];
    const float* b1 = (const float*)d_in[10];
    const float* w2 = (const float*)d_in[11];
    const float* b2 = (const float*)d_in[12];
    const float* g1 = (const float*)d_in[13];
    const float* be1 = (const float*)d_in[14];
    const float* g2 = (const float*)d_in[15];
    const float* be2 = (const float*)d_in[16];
    float* out = (float*)d_out;

    float *p_h1, *p_h2, *p_big, *p_bqkv;
    __nv_bfloat16 *p_h1b, *p_h2b, *p_vb, *p_attnb, *p_midb, *p_WqkvT, *p_WoT, *p_W1T, *p_W2T;
    cudaGetSymbolAddress((void**)&p_h1, g_h1);
    cudaGetSymbolAddress((void**)&p_h1b, g_h1b);
    cudaGetSymbolAddress((void**)&p_h2, g_h2);
    cudaGetSymbolAddress((void**)&p_h2b, g_h2b);
    cudaGetSymbolAddress((void**)&p_big, g_big);
    cudaGetSymbolAddress((void**)&p_vb, g_vb);
    cudaGetSymbolAddress((void**)&p_attnb, g_attnb);
    cudaGetSymbolAddress((void**)&p_midb, g_midb);
    cudaGetSymbolAddress((void**)&p_WqkvT, g_WqkvT);
    cudaGetSymbolAddress((void**)&p_bqkv, g_bqkv);
    cudaGetSymbolAddress((void**)&p_WoT, g_WoT);
    cudaGetSymbolAddress((void**)&p_W1T, g_W1T);
    cudaGetSymbolAddress((void**)&p_W2T, g_W2T);

    cudaFuncSetAttribute(bgemm<true, false, false, false, true>,
                         cudaFuncAttributeMaxDynamicSharedMemorySize, BG_SMEM);
    cudaFuncSetAttribute(bgemm<true, false, true, true, false>,
                         cudaFuncAttributeMaxDynamicSharedMemorySize, BG_SMEM);
    cudaFuncSetAttribute(bgemm<true, true, false, false, false>,
                         cudaFuncAttributeMaxDynamicSharedMemorySize, BG_SMEM);
    cudaFuncSetAttribute(oproj_ln_kernel,
                         cudaFuncAttributeMaxDynamicSharedMemorySize, OP_SMEM_TOTAL);

    // 0. weight repacks -> bf16 [N][K]
    pack_qkvT_kernel<<<(QKV_N * D_MODEL + 255) / 256, 256>>>(wq, wk, wv, bq, bk, bv);
    transpose_all_kernel<<<(TR_TOTAL + 255) / 256, 256>>>(wo, w1, w2);

    // 1. LN1: x -> h1 (fp32) + h1b (bf16)
    ln_kernel<<<(M_TOK * 32) / 256, 256>>>(x, g1, be1, p_h1, p_h1b);

    // 2. QKV GEMM: Q,K fp32 -> g_big; V bf16 -> g_vb
    bgemm<true, false, false, false, true><<<dim3(QKV_N / 128, M_TOK / 128), 256, BG_SMEM>>>(
        p_h1b, p_WqkvT, p_bqkv, nullptr, p_big, p_vb, QKV_N, D_MODEL);

    // 3. attention (tensor-core) -> attnb (bf16)
    attn_kernel<<<BATCH * NH, 128>>>(p_attnb);

    // 4. fused O-proj + residual + LN2 -> h2 (fp32) + h2b (bf16)
    oproj_ln_kernel<<<M_TOK / 128, 512, OP_SMEM_TOTAL>>>(
        p_attnb, p_WoT, bo, p_h1, g2, be2, p_h2, p_h2b);

    // 5. FF1 + ReLU: h2b @ W1T^T + b1 -> midb (bf16)
    bgemm<true, false, true, true, false><<<dim3(D_FF / 128, M_TOK / 128), 256, BG_SMEM>>>(
        p_h2b, p_W1T, b1, nullptr, p_midb, nullptr, D_FF, D_MODEL);

    // 6. FF2 + bias + residual: midb @ W2T^T + b2 + h2 -> out (fp32)
    bgemm<true, true, false, false, false><<<dim3(D_MODEL / 128, M_TOK / 128), 256, BG_SMEM>>>(
        p_midb, p_W2T, b2, p_h2, out, nullptr, D_MODEL, D_FF);
}